// round 10
// baseline (speedup 1.0000x reference)
#include <cuda_runtime.h>
#include <math.h>

// Problem constants
#define BQ   2
#define TT   4096
#define CC   2048
#define DD   64
#define MTOK (BQ*TT)      // 8192 tokens
#define LCH  32
#define NCH  (TT/LCH)     // 128 chunks per batch

// ---------------- device scratch ----------------
__device__ __align__(16) float g_y [MTOK*160];       // tanh mix features (tf32-rounded)
__device__ __align__(16) float g_t [MTOK*DD];        // tanh(decay proj)
__device__ __align__(16) float g_r [MTOK*DD];
__device__ __align__(16) float g_k [MTOK*DD];
__device__ __align__(16) float g_v [MTOK*DD];
__device__ __align__(16) float g_gv[MTOK*DD];
__device__ __align__(16) float g_w [MTOK*DD];
__device__ __align__(16) float g_M [BQ*NCH*DD*DD];
__device__ __align__(16) float g_S [BQ*NCH*DD*DD];
__device__ __align__(16) float g_P [BQ*NCH*DD];
__device__ __align__(16) float g_o [MTOK*DD];

// ---------------- tf32 mma helpers ----------------
__device__ __forceinline__ float tf32r(float x) {
    unsigned u;
    asm("cvt.rna.tf32.f32 %0, %1;" : "=r"(u) : "f"(x));
    return __uint_as_float(u);
}
__device__ __forceinline__ void mma8(float* d,
    unsigned a0, unsigned a1, unsigned a2, unsigned a3,
    unsigned b0, unsigned b1)
{
    asm volatile(
        "mma.sync.aligned.m16n8k8.row.col.f32.tf32.tf32.f32 "
        "{%0,%1,%2,%3}, {%4,%5,%6,%7}, {%8,%9}, {%0,%1,%2,%3};"
        : "+f"(d[0]), "+f"(d[1]), "+f"(d[2]), "+f"(d[3])
        : "r"(a0), "r"(a1), "r"(a2), "r"(a3), "r"(b0), "r"(b1));
}
#define FB(x) __float_as_uint(x)

// =====================================================================
// K1 (proven v2): y = tanh( (hs + xx*maa_x) @ w1 ), BM=32, reg-prefetch
// =====================================================================
__global__ __launch_bounds__(256) void k1_mix(
    const float* __restrict__ hs, const float* __restrict__ shift,
    const float* __restrict__ maa_x, const float* __restrict__ w1)
{
    __shared__ float x_s [32*36];
    __shared__ float w1_s[32*168];
    const int tid  = threadIdx.x;
    const int lane = tid & 31, wid = tid >> 5;
    const int gi   = lane >> 2, t = lane & 3;
    const int m0   = blockIdx.x * 32;
    const int mt   = wid & 1;
    const int ng   = wid >> 1;

    float acc[5][4];
    #pragma unroll
    for (int j = 0; j < 5; j++)
        #pragma unroll
        for (int e = 0; e < 4; e++) acc[j][e] = 0.f;

    float px[4], pw[20];
    #pragma unroll
    for (int u = 0; u < 4; u++) {
        int idx = tid + 256*u, i = idx >> 5, kk = idx & 31;
        int m = m0 + i, c = kk;
        float cur  = hs[(size_t)m*CC + c];
        float prev = ((m & (TT-1)) == 0) ? shift[(m>>12)*CC + c]
                                         : hs[(size_t)(m-1)*CC + c];
        px[u] = tf32r(cur + (prev - cur) * __ldg(&maa_x[c]));
    }
    #pragma unroll
    for (int u = 0; u < 20; u++) {
        int idx = tid + 256*u, kk = idx/160, n = idx - kk*160;
        pw[u] = tf32r(w1[(size_t)kk*160 + n]);
    }

    for (int k0 = 0; k0 < CC; k0 += 32) {
        __syncthreads();
        #pragma unroll
        for (int u = 0; u < 4; u++) {
            int idx = tid + 256*u;
            x_s[(idx >> 5)*36 + (idx & 31)] = px[u];
        }
        #pragma unroll
        for (int u = 0; u < 20; u++) {
            int idx = tid + 256*u, kk = idx/160, n = idx - kk*160;
            w1_s[kk*168 + n] = pw[u];
        }
        __syncthreads();
        const int kn = k0 + 32;
        if (kn < CC) {
            #pragma unroll
            for (int u = 0; u < 4; u++) {
                int idx = tid + 256*u, i = idx >> 5, kk = idx & 31;
                int m = m0 + i, c = kn + kk;
                float cur  = hs[(size_t)m*CC + c];
                float prev = ((m & (TT-1)) == 0) ? shift[(m>>12)*CC + c]
                                                 : hs[(size_t)(m-1)*CC + c];
                px[u] = tf32r(cur + (prev - cur) * __ldg(&maa_x[c]));
            }
            #pragma unroll
            for (int u = 0; u < 20; u++) {
                int idx = tid + 256*u, kk = idx/160, n = idx - kk*160;
                pw[u] = tf32r(w1[(size_t)(kn+kk)*160 + n]);
            }
        }
        #pragma unroll
        for (int ks = 0; ks < 4; ks++) {
            const float* Ab = x_s + (mt*16)*36 + ks*8;
            unsigned a0 = FB(Ab[gi*36 + t]);
            unsigned a1 = FB(Ab[(gi+8)*36 + t]);
            unsigned a2 = FB(Ab[gi*36 + t + 4]);
            unsigned a3 = FB(Ab[(gi+8)*36 + t + 4]);
            #pragma unroll
            for (int j = 0; j < 5; j++) {
                int n0 = ng*40 + j*8;
                unsigned b0 = FB(w1_s[(ks*8+t)*168 + n0 + gi]);
                unsigned b1 = FB(w1_s[(ks*8+t+4)*168 + n0 + gi]);
                mma8(acc[j], a0,a1,a2,a3, b0,b1);
            }
        }
    }
    const int mrow = m0 + mt*16 + gi;
    #pragma unroll
    for (int j = 0; j < 5; j++) {
        int n = ng*40 + j*8 + t*2;
        g_y[(size_t)mrow*160 + n]       = tf32r(tanhf(acc[j][0]));
        g_y[(size_t)mrow*160 + n + 1]   = tf32r(tanhf(acc[j][1]));
        g_y[(size_t)(mrow+8)*160 + n]   = tf32r(tanhf(acc[j][2]));
        g_y[(size_t)(mrow+8)*160 + n+1] = tf32r(tanhf(acc[j][3]));
    }
}

// =====================================================================
// KP v3: per (128 tokens, one field f); register double-buffered loads.
//   y_f slice staged ONCE; loop 64 c-chunks of 32:
//     regs->smem (hs 129x32, w2 32x32, W 32x64, maa) ; prefetch next chunk
//     phase A: m = y @ w2 (mma) -> A built in smem (warp-local rows)
//     phase B: acc += A @ W  (mma)  [warp-local, no block barrier A->B]
// =====================================================================
#define KP_Y   (128*36)
#define KP_HS  (129*36)
#define KP_ST  (128*36)
#define KP_W2  (32*40)
#define KP_W   (32*72)
#define KP_SMEM_FLOATS (KP_Y + KP_HS + KP_ST + KP_W2 + KP_W + 32)
#define KP_SMEM_BYTES  (KP_SMEM_FLOATS*4)

__global__ __launch_bounds__(256) void kp_proj(
    const float* __restrict__ hs, const float* __restrict__ shift,
    const float* __restrict__ maa_w, const float* __restrict__ maa_k,
    const float* __restrict__ maa_v, const float* __restrict__ maa_r,
    const float* __restrict__ maa_g, const float* __restrict__ w2,
    const float* __restrict__ dw1,  const float* __restrict__ Wk,
    const float* __restrict__ Wv,   const float* __restrict__ Wr,
    const float* __restrict__ Wg)
{
    extern __shared__ float sm[];
    float* y_s   = sm;               // [128][36]
    float* hs_s  = y_s  + KP_Y;      // [129][36] row i <-> token m0-1+i
    float* st_s  = hs_s + KP_HS;     // [128][36] A staging
    float* w2_s  = st_s + KP_ST;     // [32][40]  [d][c]
    float* W_s   = w2_s + KP_W2;     // [32][72]  [kk][n]
    float* maa_s = W_s  + KP_W;      // [32]

    const int tid  = threadIdx.x;
    const int lane = tid & 31, wid = tid >> 5;   // 8 warps, warp = 16-token tile
    const int gi   = lane >> 2, t = lane & 3;
    const int m0   = blockIdx.x * 128;
    const int f    = blockIdx.y;

    const float* mp = (f==0) ? maa_w : (f==1) ? maa_k : (f==2) ? maa_v
                     : (f==3) ? maa_r : maa_g;
    const float* Wf = (f==0) ? dw1 : (f==1) ? Wk : (f==2) ? Wv
                     : (f==3) ? Wr : Wg;

    // stage y_f slice once (row = 128B, coalesced)
    for (int idx = tid; idx < 128*32; idx += 256) {
        int i = idx >> 5, kk = idx & 31;
        y_s[i*36 + kk] = g_y[(size_t)(m0+i)*160 + f*32 + kk];
    }

    float acc[8][4];
    #pragma unroll
    for (int j = 0; j < 8; j++)
        #pragma unroll
        for (int e = 0; e < 4; e++) acc[j][e] = 0.f;

    // ---------- prefetch chunk 0 into registers ----------
    float ph[17], pw2[4], pW[8], pm;
    #pragma unroll
    for (int u = 0; u < 17; u++) {
        int idx = tid + 256*u;
        if (idx < 129*32) {
            int i = idx >> 5, c = idx & 31;
            if (i == 0 && (m0 & (TT-1)) == 0)
                ph[u] = shift[(m0 >> 12)*CC + c];
            else
                ph[u] = hs[(size_t)(m0 - 1 + i)*CC + c];
        }
    }
    #pragma unroll
    for (int u = 0; u < 4; u++) {
        int idx = tid + 256*u, d = idx >> 5, c = idx & 31;
        pw2[u] = tf32r(w2[(size_t)(f*32 + d)*CC + c]);
    }
    #pragma unroll
    for (int u = 0; u < 8; u++) {
        int idx = tid + 256*u, kk = idx >> 6, n = idx & 63;
        pW[u] = tf32r(Wf[(size_t)kk*64 + n]);
    }
    pm = (tid < 32) ? mp[tid] : 0.f;

    for (int c0 = 0; c0 < CC; c0 += 32) {
        __syncthreads();   // prev chunk's smem reads done (and y_s stage, c0=0)
        #pragma unroll
        for (int u = 0; u < 17; u++) {
            int idx = tid + 256*u;
            if (idx < 129*32) hs_s[(idx >> 5)*36 + (idx & 31)] = ph[u];
        }
        #pragma unroll
        for (int u = 0; u < 4; u++) {
            int idx = tid + 256*u;
            w2_s[(idx >> 5)*40 + (idx & 31)] = pw2[u];
        }
        #pragma unroll
        for (int u = 0; u < 8; u++) {
            int idx = tid + 256*u;
            W_s[(idx >> 6)*72 + (idx & 63)] = pW[u];
        }
        if (tid < 32) maa_s[tid] = pm;
        __syncthreads();

        // ---------- prefetch next chunk ----------
        const int cn = c0 + 32;
        if (cn < CC) {
            #pragma unroll
            for (int u = 0; u < 17; u++) {
                int idx = tid + 256*u;
                if (idx < 129*32) {
                    int i = idx >> 5, c = cn + (idx & 31);
                    if (i == 0 && (m0 & (TT-1)) == 0)
                        ph[u] = shift[(m0 >> 12)*CC + c];
                    else
                        ph[u] = hs[(size_t)(m0 - 1 + i)*CC + c];
                }
            }
            #pragma unroll
            for (int u = 0; u < 4; u++) {
                int idx = tid + 256*u, d = idx >> 5, c = idx & 31;
                pw2[u] = tf32r(w2[(size_t)(f*32 + d)*CC + cn + c]);
            }
            #pragma unroll
            for (int u = 0; u < 8; u++) {
                int idx = tid + 256*u, kk = idx >> 6, n = idx & 63;
                pW[u] = tf32r(Wf[(size_t)(cn+kk)*64 + n]);
            }
            if (tid < 32) pm = mp[cn + tid];
        }

        // phase A: m(16x32 per warp) = y(16x32) @ w2(32x32)
        float accA[4][4];
        #pragma unroll
        for (int j = 0; j < 4; j++)
            #pragma unroll
            for (int e = 0; e < 4; e++) accA[j][e] = 0.f;
        #pragma unroll
        for (int ks = 0; ks < 4; ks++) {
            const float* Ab = y_s + (wid*16)*36 + ks*8;
            unsigned a0 = FB(Ab[gi*36 + t]);
            unsigned a1 = FB(Ab[(gi+8)*36 + t]);
            unsigned a2 = FB(Ab[gi*36 + t + 4]);
            unsigned a3 = FB(Ab[(gi+8)*36 + t + 4]);
            #pragma unroll
            for (int j = 0; j < 4; j++) {
                unsigned b0 = FB(w2_s[(ks*8+t)*40   + j*8 + gi]);
                unsigned b1 = FB(w2_s[(ks*8+t+4)*40 + j*8 + gi]);
                mma8(accA[j], a0,a1,a2,a3, b0,b1);
            }
        }
        // build A rows wid*16..+15 (warp-local)
        #pragma unroll
        for (int j = 0; j < 4; j++) {
            #pragma unroll
            for (int e = 0; e < 4; e++) {
                int r = wid*16 + gi + ((e & 2) ? 8 : 0);
                int c = j*8 + t*2 + (e & 1);
                float cur  = hs_s[(r+1)*36 + c];
                float prev = hs_s[r*36 + c];
                st_s[r*36 + c] = tf32r(cur + (prev - cur)*(maa_s[c] + accA[j][e]));
            }
        }
        __syncwarp();   // cross-lane visibility of st_s within the warp

        // phase B: acc(16x64) += A(16x32) @ W(32x64); same warp-local rows
        #pragma unroll
        for (int ks = 0; ks < 4; ks++) {
            const float* Ab = st_s + (wid*16)*36 + ks*8;
            unsigned a0 = FB(Ab[gi*36 + t]);
            unsigned a1 = FB(Ab[(gi+8)*36 + t]);
            unsigned a2 = FB(Ab[gi*36 + t + 4]);
            unsigned a3 = FB(Ab[(gi+8)*36 + t + 4]);
            #pragma unroll
            for (int j = 0; j < 8; j++) {
                unsigned b0 = FB(W_s[(ks*8+t)*72   + j*8 + gi]);
                unsigned b1 = FB(W_s[(ks*8+t+4)*72 + j*8 + gi]);
                mma8(acc[j], a0,a1,a2,a3, b0,b1);
            }
        }
    }

    // epilogue: field activation
    #pragma unroll
    for (int j = 0; j < 8; j++) {
        #pragma unroll
        for (int e = 0; e < 4; e++) {
            int m = m0 + wid*16 + gi + ((e & 2) ? 8 : 0);
            int n = j*8 + t*2 + (e & 1);
            size_t ad = (size_t)m*64 + n;
            float x = acc[j][e];
            if      (f == 1) g_k[ad] = x;
            else if (f == 2) g_v[ad] = x;
            else if (f == 3) g_r[ad] = x;
            else if (f == 4) g_gv[ad] = x / (1.f + expf(-x));
            else             g_t[ad] = tf32r(tanhf(x));
        }
    }
}

// =====================================================================
// K2b (proven): g_w = -exp(tdecay + g_t @ dw2)
// =====================================================================
#define K2B_SMEM_BYTES ((128*68 + 64*72)*4)
__global__ __launch_bounds__(256) void k2b_decay(
    const float* __restrict__ dw2, const float* __restrict__ tdecay)
{
    extern __shared__ float smb[];
    float* t_s   = smb;
    float* dw2_s = t_s + 128*68;
    const int tid  = threadIdx.x;
    const int lane = tid & 31, wid = tid >> 5;
    const int gi   = lane >> 2, t = lane & 3;
    const int m0   = blockIdx.x * 128;

    for (int idx = tid; idx < 8192; idx += 256) {
        int i = idx >> 6, d = idx & 63;
        t_s[i*68 + d] = g_t[(size_t)(m0+i)*64 + d];
    }
    for (int idx = tid; idx < 4096; idx += 256) {
        int d = idx >> 6, n = idx & 63;
        dw2_s[d*72 + n] = tf32r(dw2[idx]);
    }
    __syncthreads();

    float acc[8][4];
    #pragma unroll
    for (int j = 0; j < 8; j++)
        #pragma unroll
        for (int e = 0; e < 4; e++) acc[j][e] = 0.f;

    #pragma unroll
    for (int ks = 0; ks < 8; ks++) {
        const float* Ab = t_s + (wid*16)*68 + ks*8;
        unsigned a0 = FB(Ab[gi*68 + t]);
        unsigned a1 = FB(Ab[(gi+8)*68 + t]);
        unsigned a2 = FB(Ab[gi*68 + t + 4]);
        unsigned a3 = FB(Ab[(gi+8)*68 + t + 4]);
        #pragma unroll
        for (int j = 0; j < 8; j++) {
            unsigned b0 = FB(dw2_s[(ks*8+t)*72 + j*8 + gi]);
            unsigned b1 = FB(dw2_s[(ks*8+t+4)*72 + j*8 + gi]);
            mma8(acc[j], a0,a1,a2,a3, b0,b1);
        }
    }
    #pragma unroll
    for (int j = 0; j < 8; j++) {
        #pragma unroll
        for (int e = 0; e < 4; e++) {
            int m = m0 + wid*16 + gi + ((e & 2) ? 8 : 0);
            int n = j*8 + t*2 + (e & 1);
            g_w[(size_t)m*64 + n] = -expf(__ldg(&tdecay[n]) + acc[j][e]);
        }
    }
}

// =====================================================================
// K3 (proven)
// =====================================================================
__global__ __launch_bounds__(256,1) void k3_chunk()
{
    __shared__ float k_s[32*64], v_s[32*64], cum_s[32*64], kh_s[32*64];
    const int bc   = blockIdx.x;
    const int tok0 = bc * 32;
    const int tid  = threadIdx.x;

    for (int idx = tid; idx < 2048; idx += 256) {
        size_t g = (size_t)tok0*64 + idx;
        k_s[idx]   = g_k[g];
        v_s[idx]   = g_v[g];
        cum_s[idx] = g_w[g];
    }
    __syncthreads();
    if (tid < 64) {
        float c = 0.f;
        for (int i = 0; i < 32; i++) { c += cum_s[i*64 + tid]; cum_s[i*64 + tid] = c; }
        g_P[bc*64 + tid] = expf(c);
        for (int i = 0; i < 32; i++)
            kh_s[i*64 + tid] = k_s[i*64 + tid] * expf(c - cum_s[i*64 + tid]);
    }
    __syncthreads();
    for (int it = 0; it < 16; it++) {
        int e  = tid + 256*it;
        int dk = e >> 6, dv = e & 63;
        float s = 0.f;
        #pragma unroll
        for (int i = 0; i < 32; i++)
            s += kh_s[i*64 + dk] * v_s[i*64 + dv];
        g_M[(size_t)bc*4096 + e] = s;
    }
}

// =====================================================================
// K4 (proven + k7 folded in): inter-chunk scan, prefetch depth 32
// =====================================================================
__global__ __launch_bounds__(256,1) void k4_scan(
    const float* __restrict__ wkv0, float* __restrict__ out_sf,
    const float* __restrict__ hs,   float* __restrict__ out_lx)
{
    const int e  = blockIdx.x*256 + threadIdx.x;
    const int b  = e >> 12, eb = e & 4095, dk = eb >> 6;
    float sv = wkv0[e];
    const float* Mp = g_M + (size_t)b*NCH*4096 + eb;
    const float* Pp = g_P + b*NCH*64 + dk;
    float*       Sp = g_S + (size_t)b*NCH*4096 + eb;

    // folded k7: lx = hs[:, -1, :]
    if (e < BQ*CC) {
        int bb = e >> 11, c = e & 2047;
        out_lx[e] = hs[((size_t)bb*TT + (TT-1))*CC + c];
    }

    float mq[32], pq[32];
    #pragma unroll
    for (int q = 0; q < 32; q++) { mq[q] = Mp[(size_t)q*4096]; pq[q] = Pp[q*64]; }

    for (int c = 0; c < NCH; c += 32) {
        #pragma unroll
        for (int q = 0; q < 32; q++) {
            Sp[(size_t)(c+q)*4096] = sv;
            sv = sv*pq[q] + mq[q];
            int cn = c + q + 32;
            if (cn < NCH) { mq[q] = Mp[(size_t)cn*4096]; pq[q] = Pp[cn*64]; }
        }
    }
    out_sf[e] = sv;
}

// =====================================================================
// K5 (proven)
// =====================================================================
#define K5_SMEM_FLOATS (4*(32*65) + 64*65 + 32*33 + 32)
#define K5_SMEM_BYTES  (K5_SMEM_FLOATS*4)

__global__ __launch_bounds__(256,1) void k5_intra(const float* __restrict__ faaaa)
{
    extern __shared__ float sm5[];
    float* r_s    = sm5;
    float* k_s    = r_s   + 32*65;
    float* v_s    = k_s   + 32*65;
    float* cum_s  = v_s   + 32*65;
    float* S_s    = cum_s + 32*65;
    float* sc_s   = S_s   + 64*65;
    float* diag_s = sc_s  + 32*33;

    const int bc   = blockIdx.x;
    const int tok0 = bc * 32;
    const int tid  = threadIdx.x;

    for (int idx = tid; idx < 2048; idx += 256) {
        int i = idx >> 6, d = idx & 63;
        size_t g = (size_t)tok0*64 + idx;
        r_s[i*65 + d]   = g_r[g];
        k_s[i*65 + d]   = g_k[g];
        v_s[i*65 + d]   = g_v[g];
        cum_s[i*65 + d] = g_w[g];
    }
    for (int idx = tid; idx < 4096; idx += 256) {
        int dk = idx >> 6, dv = idx & 63;
        S_s[dk*65 + dv] = g_S[(size_t)bc*4096 + idx];
    }
    __syncthreads();
    if (tid < 64) {
        float c = 0.f;
        for (int i = 0; i < 32; i++) { c += cum_s[i*65 + tid]; cum_s[i*65 + tid] = c; }
    }
    __syncthreads();
    if (tid < 32) {
        float s = 0.f;
        #pragma unroll
        for (int d = 0; d < 64; d++)
            s += r_s[tid*65 + d] * __ldg(&faaaa[d]) * k_s[tid*65 + d];
        diag_s[tid] = s;
    }
    __syncthreads();
    for (int idx = tid; idx < 2048; idx += 256) {
        int i = idx >> 6, d = idx & 63;
        float ce = (i == 0) ? 0.f : cum_s[(i-1)*65 + d];
        r_s[i*65 + d] *= expf(ce);
        k_s[i*65 + d] *= expf(-cum_s[i*65 + d]);
    }
    __syncthreads();
    #pragma unroll
    for (int q = 0; q < 4; q++) {
        int idx = tid + 256*q;
        int i = idx >> 5, j = idx & 31;
        float val;
        if (j < i) {
            float s = 0.f;
            #pragma unroll
            for (int d = 0; d < 64; d++)
                s += r_s[i*65 + d] * k_s[j*65 + d];
            val = s;
        } else {
            val = (j == i) ? diag_s[i] : 0.f;
        }
        sc_s[i*33 + j] = val;
    }
    __syncthreads();
    #pragma unroll
    for (int q = 0; q < 8; q++) {
        int idx = tid + 256*q;
        int i = idx >> 6, dv = idx & 63;
        float o = 0.f;
        #pragma unroll
        for (int j = 0; j < 32; j++)
            o += sc_s[i*33 + j] * v_s[j*65 + dv];
        #pragma unroll
        for (int d = 0; d < 64; d++)
            o += r_s[i*65 + d] * S_s[d*65 + dv];
        g_o[(size_t)tok0*64 + idx] = o;
    }
}

// =====================================================================
// K6 (proven): out = (o * g) @ W_o via tf32 mma, 128x128 tile
// =====================================================================
#define K6_SMEM_BYTES ((128*68 + 64*136)*4)
__global__ __launch_bounds__(256,1) void k6_out(
    const float* __restrict__ Wo, float* __restrict__ out)
{
    extern __shared__ float sm6[];
    float* a_s = sm6;
    float* b_s = a_s + 128*68;

    const int tid  = threadIdx.x;
    const int lane = tid & 31, wid = tid >> 5;
    const int gi   = lane >> 2, t = lane & 3;
    const int bm = blockIdx.x * 128, bn = blockIdx.y * 128;

    for (int idx = tid; idx < 8192; idx += 256) {
        int i = idx >> 6, d = idx & 63;
        size_t g = (size_t)(bm+i)*64 + d;
        a_s[i*68 + d] = tf32r(g_o[g] * g_gv[g]);
    }
    for (int idx = tid; idx < 8192; idx += 256) {
        int dd = idx >> 7, n = idx & 127;
        b_s[dd*136 + n] = tf32r(Wo[(size_t)dd*CC + bn + n]);
    }
    __syncthreads();

    const int rb = (wid & 3) * 32;
    const int n0 = (wid >> 2) * 64;
    float acc[2][8][4];
    #pragma unroll
    for (int mi = 0; mi < 2; mi++)
        #pragma unroll
        for (int j = 0; j < 8; j++)
            #pragma unroll
            for (int e = 0; e < 4; e++) acc[mi][j][e] = 0.f;

    #pragma unroll
    for (int ks = 0; ks < 8; ks++) {
        unsigned a[2][4];
        #pragma unroll
        for (int mi = 0; mi < 2; mi++) {
            const float* Ab = a_s + (rb + mi*16)*68 + ks*8;
            a[mi][0] = FB(Ab[gi*68 + t]);
            a[mi][1] = FB(Ab[(gi+8)*68 + t]);
            a[mi][2] = FB(Ab[gi*68 + t + 4]);
            a[mi][3] = FB(Ab[(gi+8)*68 + t + 4]);
        }
        #pragma unroll
        for (int j = 0; j < 8; j++) {
            unsigned b0 = FB(b_s[(ks*8+t)*136 + n0 + j*8 + gi]);
            unsigned b1 = FB(b_s[(ks*8+t+4)*136 + n0 + j*8 + gi]);
            mma8(acc[0][j], a[0][0],a[0][1],a[0][2],a[0][3], b0,b1);
            mma8(acc[1][j], a[1][0],a[1][1],a[1][2],a[1][3], b0,b1);
        }
    }
    #pragma unroll
    for (int mi = 0; mi < 2; mi++)
        #pragma unroll
        for (int j = 0; j < 8; j++) {
            int m = bm + rb + mi*16 + gi;
            int n = bn + n0 + j*8 + t*2;
            out[(size_t)m*CC + n]       = acc[mi][j][0];
            out[(size_t)m*CC + n + 1]   = acc[mi][j][1];
            out[(size_t)(m+8)*CC + n]   = acc[mi][j][2];
            out[(size_t)(m+8)*CC + n+1] = acc[mi][j][3];
        }
}

// =====================================================================
extern "C" void kernel_launch(void* const* d_in, const int* in_sizes, int n_in,
                              void* d_out, int out_size)
{
    (void)in_sizes; (void)n_in; (void)out_size;
    const float* hs     = (const float*)d_in[0];
    const float* shift  = (const float*)d_in[1];
    const float* wkv0   = (const float*)d_in[2];
    const float* maa_x  = (const float*)d_in[3];
    const float* maa_w  = (const float*)d_in[4];
    const float* maa_k  = (const float*)d_in[5];
    const float* maa_v  = (const float*)d_in[6];
    const float* maa_r  = (const float*)d_in[7];
    const float* maa_g  = (const float*)d_in[8];
    const float* w1     = (const float*)d_in[9];
    const float* w2     = (const float*)d_in[10];
    const float* tdecay = (const float*)d_in[11];
    const float* dw1    = (const float*)d_in[12];
    const float* dw2    = (const float*)d_in[13];
    const float* faaaa  = (const float*)d_in[14];
    const float* Wr     = (const float*)d_in[15];
    const float* Wk     = (const float*)d_in[16];
    const float* Wv     = (const float*)d_in[17];
    const float* Wg     = (const float*)d_in[18];
    const float* Wo     = (const float*)d_in[19];
    float* out = (float*)d_out;

    const size_t OFF_LX = (size_t)BQ*TT*CC;
    const size_t OFF_SF = OFF_LX + (size_t)BQ*CC;

    cudaFuncSetAttribute(kp_proj,   cudaFuncAttributeMaxDynamicSharedMemorySize, KP_SMEM_BYTES);
    cudaFuncSetAttribute(k2b_decay, cudaFuncAttributeMaxDynamicSharedMemorySize, K2B_SMEM_BYTES);
    cudaFuncSetAttribute(k5_intra,  cudaFuncAttributeMaxDynamicSharedMemorySize, K5_SMEM_BYTES);
    cudaFuncSetAttribute(k6_out,    cudaFuncAttributeMaxDynamicSharedMemorySize, K6_SMEM_BYTES);

    k1_mix   <<<MTOK/32, 256>>>(hs, shift, maa_x, w1);
    kp_proj  <<<dim3(MTOK/128, 5), 256, KP_SMEM_BYTES>>>(hs, shift, maa_w, maa_k,
                                                         maa_v, maa_r, maa_g, w2,
                                                         dw1, Wk, Wv, Wr, Wg);
    k2b_decay<<<MTOK/128, 256, K2B_SMEM_BYTES>>>(dw2, tdecay);
    k3_chunk <<<BQ*NCH, 256>>>();
    k4_scan  <<<32, 256>>>(wkv0, out + OFF_SF, hs, out + OFF_LX);
    k5_intra <<<BQ*NCH, 256, K5_SMEM_BYTES>>>(faaaa);
    k6_out   <<<dim3(MTOK/128, CC/128), 256, K6_SMEM_BYTES>>>(Wo, out);
}

// round 11
// speedup vs baseline: 1.0828x; 1.0828x over previous
#include <cuda_runtime.h>
#include <math.h>

// Problem constants
#define BQ   2
#define TT   4096
#define CC   2048
#define DD   64
#define MTOK (BQ*TT)      // 8192 tokens
#define LCH  32
#define NCH  (TT/LCH)     // 128 chunks per batch

// ---------------- device scratch ----------------
__device__ __align__(16) float g_y [MTOK*160];       // tanh mix features (tf32-rounded)
__device__ __align__(16) float g_r [MTOK*DD];
__device__ __align__(16) float g_k [MTOK*DD];
__device__ __align__(16) float g_v [MTOK*DD];
__device__ __align__(16) float g_gv[MTOK*DD];
__device__ __align__(16) float g_w [MTOK*DD];
__device__ __align__(16) float g_M [BQ*NCH*DD*DD];
__device__ __align__(16) float g_S [BQ*NCH*DD*DD];
__device__ __align__(16) float g_P [BQ*NCH*DD];
__device__ __align__(16) float g_o [MTOK*DD];

// ---------------- tf32 mma helpers ----------------
__device__ __forceinline__ float tf32r(float x) {
    unsigned u;
    asm("cvt.rna.tf32.f32 %0, %1;" : "=r"(u) : "f"(x));
    return __uint_as_float(u);
}
__device__ __forceinline__ void mma8(float* d,
    unsigned a0, unsigned a1, unsigned a2, unsigned a3,
    unsigned b0, unsigned b1)
{
    asm volatile(
        "mma.sync.aligned.m16n8k8.row.col.f32.tf32.tf32.f32 "
        "{%0,%1,%2,%3}, {%4,%5,%6,%7}, {%8,%9}, {%0,%1,%2,%3};"
        : "+f"(d[0]), "+f"(d[1]), "+f"(d[2]), "+f"(d[3])
        : "r"(a0), "r"(a1), "r"(a2), "r"(a3), "r"(b0), "r"(b1));
}
#define FB(x) __float_as_uint(x)

// =====================================================================
// K1 (proven v2): y = tanh( (hs + xx*maa_x) @ w1 ), BM=32, reg-prefetch
// =====================================================================
__global__ __launch_bounds__(256) void k1_mix(
    const float* __restrict__ hs, const float* __restrict__ shift,
    const float* __restrict__ maa_x, const float* __restrict__ w1)
{
    __shared__ float x_s [32*36];
    __shared__ float w1_s[32*168];
    const int tid  = threadIdx.x;
    const int lane = tid & 31, wid = tid >> 5;
    const int gi   = lane >> 2, t = lane & 3;
    const int m0   = blockIdx.x * 32;
    const int mt   = wid & 1;
    const int ng   = wid >> 1;

    float acc[5][4];
    #pragma unroll
    for (int j = 0; j < 5; j++)
        #pragma unroll
        for (int e = 0; e < 4; e++) acc[j][e] = 0.f;

    float px[4], pw[20];
    #pragma unroll
    for (int u = 0; u < 4; u++) {
        int idx = tid + 256*u, i = idx >> 5, kk = idx & 31;
        int m = m0 + i, c = kk;
        float cur  = hs[(size_t)m*CC + c];
        float prev = ((m & (TT-1)) == 0) ? shift[(m>>12)*CC + c]
                                         : hs[(size_t)(m-1)*CC + c];
        px[u] = tf32r(cur + (prev - cur) * __ldg(&maa_x[c]));
    }
    #pragma unroll
    for (int u = 0; u < 20; u++) {
        int idx = tid + 256*u, kk = idx/160, n = idx - kk*160;
        pw[u] = tf32r(w1[(size_t)kk*160 + n]);
    }

    for (int k0 = 0; k0 < CC; k0 += 32) {
        __syncthreads();
        #pragma unroll
        for (int u = 0; u < 4; u++) {
            int idx = tid + 256*u;
            x_s[(idx >> 5)*36 + (idx & 31)] = px[u];
        }
        #pragma unroll
        for (int u = 0; u < 20; u++) {
            int idx = tid + 256*u, kk = idx/160, n = idx - kk*160;
            w1_s[kk*168 + n] = pw[u];
        }
        __syncthreads();
        const int kn = k0 + 32;
        if (kn < CC) {
            #pragma unroll
            for (int u = 0; u < 4; u++) {
                int idx = tid + 256*u, i = idx >> 5, kk = idx & 31;
                int m = m0 + i, c = kn + kk;
                float cur  = hs[(size_t)m*CC + c];
                float prev = ((m & (TT-1)) == 0) ? shift[(m>>12)*CC + c]
                                                 : hs[(size_t)(m-1)*CC + c];
                px[u] = tf32r(cur + (prev - cur) * __ldg(&maa_x[c]));
            }
            #pragma unroll
            for (int u = 0; u < 20; u++) {
                int idx = tid + 256*u, kk = idx/160, n = idx - kk*160;
                pw[u] = tf32r(w1[(size_t)(kn+kk)*160 + n]);
            }
        }
        #pragma unroll
        for (int ks = 0; ks < 4; ks++) {
            const float* Ab = x_s + (mt*16)*36 + ks*8;
            unsigned a0 = FB(Ab[gi*36 + t]);
            unsigned a1 = FB(Ab[(gi+8)*36 + t]);
            unsigned a2 = FB(Ab[gi*36 + t + 4]);
            unsigned a3 = FB(Ab[(gi+8)*36 + t + 4]);
            #pragma unroll
            for (int j = 0; j < 5; j++) {
                int n0 = ng*40 + j*8;
                unsigned b0 = FB(w1_s[(ks*8+t)*168 + n0 + gi]);
                unsigned b1 = FB(w1_s[(ks*8+t+4)*168 + n0 + gi]);
                mma8(acc[j], a0,a1,a2,a3, b0,b1);
            }
        }
    }
    const int mrow = m0 + mt*16 + gi;
    #pragma unroll
    for (int j = 0; j < 5; j++) {
        int n = ng*40 + j*8 + t*2;
        g_y[(size_t)mrow*160 + n]       = tf32r(tanhf(acc[j][0]));
        g_y[(size_t)mrow*160 + n + 1]   = tf32r(tanhf(acc[j][1]));
        g_y[(size_t)(mrow+8)*160 + n]   = tf32r(tanhf(acc[j][2]));
        g_y[(size_t)(mrow+8)*160 + n+1] = tf32r(tanhf(acc[j][3]));
    }
}

// =====================================================================
// KP (R9-proven main loop + folded decay GEMM in f==0 epilogue):
// per (128 tokens, one field f):
//   y_f slice staged ONCE; loop 64 c-chunks of 32:
//     load hs(129x32), w2_f(32x32), W_f(32x64)
//     phase A: m = y @ w2 (mma) -> A built in smem (warp-local rows)
//     phase B: acc += A @ W  (mma)   [no block barrier A->B]
//   epilogue: f!=0 -> activations to globals
//             f==0 -> tanh to smem, then g_w = -exp(tdecay + T @ dw2)
// =====================================================================
#define KP_Y   (128*36)
#define KP_HS  (129*36)
#define KP_ST  (128*36)
#define KP_W2  (32*40)
#define KP_W   (32*72)
#define KP_SMEM_FLOATS (KP_Y + KP_HS + KP_ST + KP_W2 + KP_W + 32)
#define KP_SMEM_BYTES  (KP_SMEM_FLOATS*4)

__global__ __launch_bounds__(256) void kp_proj(
    const float* __restrict__ hs, const float* __restrict__ shift,
    const float* __restrict__ maa_w, const float* __restrict__ maa_k,
    const float* __restrict__ maa_v, const float* __restrict__ maa_r,
    const float* __restrict__ maa_g, const float* __restrict__ w2,
    const float* __restrict__ dw1,  const float* __restrict__ Wk,
    const float* __restrict__ Wv,   const float* __restrict__ Wr,
    const float* __restrict__ Wg,   const float* __restrict__ dw2,
    const float* __restrict__ tdecay)
{
    extern __shared__ float sm[];
    float* y_s   = sm;               // [128][36]
    float* hs_s  = y_s  + KP_Y;      // [129][36] row i <-> token m0-1+i
    float* st_s  = hs_s + KP_HS;     // [128][36] A staging
    float* w2_s  = st_s + KP_ST;     // [32][40]  [d][c]
    float* W_s   = w2_s + KP_W2;     // [32][72]  [kk][n]
    float* maa_s = W_s  + KP_W;      // [32]

    const int tid  = threadIdx.x;
    const int lane = tid & 31, wid = tid >> 5;   // 8 warps, warp = 16-token tile
    const int gi   = lane >> 2, t = lane & 3;
    const int m0   = blockIdx.x * 128;
    const int f    = blockIdx.y;

    const float* mp = (f==0) ? maa_w : (f==1) ? maa_k : (f==2) ? maa_v
                     : (f==3) ? maa_r : maa_g;
    const float* Wf = (f==0) ? dw1 : (f==1) ? Wk : (f==2) ? Wv
                     : (f==3) ? Wr : Wg;

    // stage y_f slice once (row = 128B, coalesced)
    for (int idx = tid; idx < 128*32; idx += 256) {
        int i = idx >> 5, kk = idx & 31;
        y_s[i*36 + kk] = g_y[(size_t)(m0+i)*160 + f*32 + kk];
    }

    float acc[8][4];
    #pragma unroll
    for (int j = 0; j < 8; j++)
        #pragma unroll
        for (int e = 0; e < 4; e++) acc[j][e] = 0.f;

    for (int c0 = 0; c0 < CC; c0 += 32) {
        __syncthreads();   // prev chunk consumed (covers y_s stage before 1st use)
        // hs tile rows m0-1 .. m0+127, cols c0..c0+31 (128B rows)
        for (int idx = tid; idx < 129*32; idx += 256) {
            int i = idx >> 5, c = idx & 31;
            float v;
            if (i == 0 && (m0 & (TT-1)) == 0)
                v = shift[(m0 >> 12)*CC + c0 + c];
            else
                v = hs[(size_t)(m0 - 1 + i)*CC + c0 + c];
            hs_s[i*36 + c] = v;
        }
        for (int idx = tid; idx < 1024; idx += 256) {
            int d = idx >> 5, c = idx & 31;
            w2_s[d*40 + c] = tf32r(w2[(size_t)(f*32 + d)*CC + c0 + c]);
        }
        for (int idx = tid; idx < 2048; idx += 256) {
            int kk = idx >> 6, n = idx & 63;
            W_s[kk*72 + n] = tf32r(Wf[(size_t)(c0+kk)*64 + n]);
        }
        if (tid < 32) maa_s[tid] = mp[c0 + tid];
        __syncthreads();

        // phase A: m(16x32 per warp) = y(16x32) @ w2(32x32)
        float accA[4][4];
        #pragma unroll
        for (int j = 0; j < 4; j++)
            #pragma unroll
            for (int e = 0; e < 4; e++) accA[j][e] = 0.f;
        #pragma unroll
        for (int ks = 0; ks < 4; ks++) {
            const float* Ab = y_s + (wid*16)*36 + ks*8;
            unsigned a0 = FB(Ab[gi*36 + t]);
            unsigned a1 = FB(Ab[(gi+8)*36 + t]);
            unsigned a2 = FB(Ab[gi*36 + t + 4]);
            unsigned a3 = FB(Ab[(gi+8)*36 + t + 4]);
            #pragma unroll
            for (int j = 0; j < 4; j++) {
                unsigned b0 = FB(w2_s[(ks*8+t)*40   + j*8 + gi]);
                unsigned b1 = FB(w2_s[(ks*8+t+4)*40 + j*8 + gi]);
                mma8(accA[j], a0,a1,a2,a3, b0,b1);
            }
        }
        // build A rows wid*16..+15 (warp-local)
        #pragma unroll
        for (int j = 0; j < 4; j++) {
            #pragma unroll
            for (int e = 0; e < 4; e++) {
                int r = wid*16 + gi + ((e & 2) ? 8 : 0);
                int c = j*8 + t*2 + (e & 1);
                float cur  = hs_s[(r+1)*36 + c];
                float prev = hs_s[r*36 + c];
                st_s[r*36 + c] = tf32r(cur + (prev - cur)*(maa_s[c] + accA[j][e]));
            }
        }
        __syncwarp();   // cross-lane visibility of st_s within the warp

        // phase B: acc(16x64) += A(16x32) @ W(32x64); same warp-local rows
        #pragma unroll
        for (int ks = 0; ks < 4; ks++) {
            const float* Ab = st_s + (wid*16)*36 + ks*8;
            unsigned a0 = FB(Ab[gi*36 + t]);
            unsigned a1 = FB(Ab[(gi+8)*36 + t]);
            unsigned a2 = FB(Ab[gi*36 + t + 4]);
            unsigned a3 = FB(Ab[(gi+8)*36 + t + 4]);
            #pragma unroll
            for (int j = 0; j < 8; j++) {
                unsigned b0 = FB(W_s[(ks*8+t)*72   + j*8 + gi]);
                unsigned b1 = FB(W_s[(ks*8+t+4)*72 + j*8 + gi]);
                mma8(acc[j], a0,a1,a2,a3, b0,b1);
            }
        }
    }

    if (f != 0) {
        // epilogue: field activation -> globals
        #pragma unroll
        for (int j = 0; j < 8; j++) {
            #pragma unroll
            for (int e = 0; e < 4; e++) {
                int m = m0 + wid*16 + gi + ((e & 2) ? 8 : 0);
                int n = j*8 + t*2 + (e & 1);
                size_t ad = (size_t)m*64 + n;
                float x = acc[j][e];
                if      (f == 1) g_k[ad] = x;
                else if (f == 2) g_v[ad] = x;
                else if (f == 3) g_r[ad] = x;
                else             g_gv[ad] = x / (1.f + expf(-x));
            }
        }
    } else {
        // folded decay path: T = tf32(tanh(acc)); g_w = -exp(tdecay + T@dw2)
        __syncthreads();                 // all warps done with y_s/hs_s/st_s
        float* T_s  = sm;                // [128][68] aliases y_s+hs_s (9252 >= 8704)
        float* d2_s = st_s;              // [64][72] = 4608 floats, exact fit
        float* td_s = W_s;               // [64]
        #pragma unroll
        for (int j = 0; j < 8; j++) {
            #pragma unroll
            for (int e = 0; e < 4; e++) {
                int r = wid*16 + gi + ((e & 2) ? 8 : 0);
                int c = j*8 + t*2 + (e & 1);
                T_s[r*68 + c] = tf32r(tanhf(acc[j][e]));
            }
        }
        for (int idx = tid; idx < 4096; idx += 256) {
            int d = idx >> 6, n = idx & 63;
            d2_s[d*72 + n] = tf32r(dw2[idx]);
        }
        if (tid < 64) td_s[tid] = tdecay[tid];
        __syncthreads();

        float acc2[8][4];
        #pragma unroll
        for (int j = 0; j < 8; j++)
            #pragma unroll
            for (int e = 0; e < 4; e++) acc2[j][e] = 0.f;
        #pragma unroll
        for (int ks = 0; ks < 8; ks++) {
            const float* Ab = T_s + (wid*16)*68 + ks*8;
            unsigned a0 = FB(Ab[gi*68 + t]);
            unsigned a1 = FB(Ab[(gi+8)*68 + t]);
            unsigned a2 = FB(Ab[gi*68 + t + 4]);
            unsigned a3 = FB(Ab[(gi+8)*68 + t + 4]);
            #pragma unroll
            for (int j = 0; j < 8; j++) {
                unsigned b0 = FB(d2_s[(ks*8+t)*72 + j*8 + gi]);
                unsigned b1 = FB(d2_s[(ks*8+t+4)*72 + j*8 + gi]);
                mma8(acc2[j], a0,a1,a2,a3, b0,b1);
            }
        }
        #pragma unroll
        for (int j = 0; j < 8; j++) {
            #pragma unroll
            for (int e = 0; e < 4; e++) {
                int m = m0 + wid*16 + gi + ((e & 2) ? 8 : 0);
                int n = j*8 + t*2 + (e & 1);
                g_w[(size_t)m*64 + n] = -expf(td_s[n] + acc2[j][e]);
            }
        }
    }
}

// =====================================================================
// K3 (proven)
// =====================================================================
__global__ __launch_bounds__(256,1) void k3_chunk()
{
    __shared__ float k_s[32*64], v_s[32*64], cum_s[32*64], kh_s[32*64];
    const int bc   = blockIdx.x;
    const int tok0 = bc * 32;
    const int tid  = threadIdx.x;

    for (int idx = tid; idx < 2048; idx += 256) {
        size_t g = (size_t)tok0*64 + idx;
        k_s[idx]   = g_k[g];
        v_s[idx]   = g_v[g];
        cum_s[idx] = g_w[g];
    }
    __syncthreads();
    if (tid < 64) {
        float c = 0.f;
        for (int i = 0; i < 32; i++) { c += cum_s[i*64 + tid]; cum_s[i*64 + tid] = c; }
        g_P[bc*64 + tid] = expf(c);
        for (int i = 0; i < 32; i++)
            kh_s[i*64 + tid] = k_s[i*64 + tid] * expf(c - cum_s[i*64 + tid]);
    }
    __syncthreads();
    for (int it = 0; it < 16; it++) {
        int e  = tid + 256*it;
        int dk = e >> 6, dv = e & 63;
        float s = 0.f;
        #pragma unroll
        for (int i = 0; i < 32; i++)
            s += kh_s[i*64 + dk] * v_s[i*64 + dv];
        g_M[(size_t)bc*4096 + e] = s;
    }
}

// =====================================================================
// K4 (proven, k7 folded): inter-chunk scan, prefetch depth 32
// =====================================================================
__global__ __launch_bounds__(256,1) void k4_scan(
    const float* __restrict__ wkv0, float* __restrict__ out_sf,
    const float* __restrict__ hs,   float* __restrict__ out_lx)
{
    const int e  = blockIdx.x*256 + threadIdx.x;
    const int b  = e >> 12, eb = e & 4095, dk = eb >> 6;
    float sv = wkv0[e];
    const float* Mp = g_M + (size_t)b*NCH*4096 + eb;
    const float* Pp = g_P + b*NCH*64 + dk;
    float*       Sp = g_S + (size_t)b*NCH*4096 + eb;

    // folded k7: lx = hs[:, -1, :]
    if (e < BQ*CC) {
        int bb = e >> 11, c = e & 2047;
        out_lx[e] = hs[((size_t)bb*TT + (TT-1))*CC + c];
    }

    float mq[32], pq[32];
    #pragma unroll
    for (int q = 0; q < 32; q++) { mq[q] = Mp[(size_t)q*4096]; pq[q] = Pp[q*64]; }

    for (int c = 0; c < NCH; c += 32) {
        #pragma unroll
        for (int q = 0; q < 32; q++) {
            Sp[(size_t)(c+q)*4096] = sv;
            sv = sv*pq[q] + mq[q];
            int cn = c + q + 32;
            if (cn < NCH) { mq[q] = Mp[(size_t)cn*4096]; pq[q] = Pp[cn*64]; }
        }
    }
    out_sf[e] = sv;
}

// =====================================================================
// K5 (proven)
// =====================================================================
#define K5_SMEM_FLOATS (4*(32*65) + 64*65 + 32*33 + 32)
#define K5_SMEM_BYTES  (K5_SMEM_FLOATS*4)

__global__ __launch_bounds__(256,1) void k5_intra(const float* __restrict__ faaaa)
{
    extern __shared__ float sm5[];
    float* r_s    = sm5;
    float* k_s    = r_s   + 32*65;
    float* v_s    = k_s   + 32*65;
    float* cum_s  = v_s   + 32*65;
    float* S_s    = cum_s + 32*65;
    float* sc_s   = S_s   + 64*65;
    float* diag_s = sc_s  + 32*33;

    const int bc   = blockIdx.x;
    const int tok0 = bc * 32;
    const int tid  = threadIdx.x;

    for (int idx = tid; idx < 2048; idx += 256) {
        int i = idx >> 6, d = idx & 63;
        size_t g = (size_t)tok0*64 + idx;
        r_s[i*65 + d]   = g_r[g];
        k_s[i*65 + d]   = g_k[g];
        v_s[i*65 + d]   = g_v[g];
        cum_s[i*65 + d] = g_w[g];
    }
    for (int idx = tid; idx < 4096; idx += 256) {
        int dk = idx >> 6, dv = idx & 63;
        S_s[dk*65 + dv] = g_S[(size_t)bc*4096 + idx];
    }
    __syncthreads();
    if (tid < 64) {
        float c = 0.f;
        for (int i = 0; i < 32; i++) { c += cum_s[i*65 + tid]; cum_s[i*65 + tid] = c; }
    }
    __syncthreads();
    if (tid < 32) {
        float s = 0.f;
        #pragma unroll
        for (int d = 0; d < 64; d++)
            s += r_s[tid*65 + d] * __ldg(&faaaa[d]) * k_s[tid*65 + d];
        diag_s[tid] = s;
    }
    __syncthreads();
    for (int idx = tid; idx < 2048; idx += 256) {
        int i = idx >> 6, d = idx & 63;
        float ce = (i == 0) ? 0.f : cum_s[(i-1)*65 + d];
        r_s[i*65 + d] *= expf(ce);
        k_s[i*65 + d] *= expf(-cum_s[i*65 + d]);
    }
    __syncthreads();
    #pragma unroll
    for (int q = 0; q < 4; q++) {
        int idx = tid + 256*q;
        int i = idx >> 5, j = idx & 31;
        float val;
        if (j < i) {
            float s = 0.f;
            #pragma unroll
            for (int d = 0; d < 64; d++)
                s += r_s[i*65 + d] * k_s[j*65 + d];
            val = s;
        } else {
            val = (j == i) ? diag_s[i] : 0.f;
        }
        sc_s[i*33 + j] = val;
    }
    __syncthreads();
    #pragma unroll
    for (int q = 0; q < 8; q++) {
        int idx = tid + 256*q;
        int i = idx >> 6, dv = idx & 63;
        float o = 0.f;
        #pragma unroll
        for (int j = 0; j < 32; j++)
            o += sc_s[i*33 + j] * v_s[j*65 + dv];
        #pragma unroll
        for (int d = 0; d < 64; d++)
            o += r_s[i*65 + d] * S_s[d*65 + dv];
        g_o[(size_t)tok0*64 + idx] = o;
    }
}

// =====================================================================
// K6 (proven): out = (o * g) @ W_o via tf32 mma, 128x128 tile
// =====================================================================
#define K6_SMEM_BYTES ((128*68 + 64*136)*4)
__global__ __launch_bounds__(256,1) void k6_out(
    const float* __restrict__ Wo, float* __restrict__ out)
{
    extern __shared__ float sm6[];
    float* a_s = sm6;
    float* b_s = a_s + 128*68;

    const int tid  = threadIdx.x;
    const int lane = tid & 31, wid = tid >> 5;
    const int gi   = lane >> 2, t = lane & 3;
    const int bm = blockIdx.x * 128, bn = blockIdx.y * 128;

    for (int idx = tid; idx < 8192; idx += 256) {
        int i = idx >> 6, d = idx & 63;
        size_t g = (size_t)(bm+i)*64 + d;
        a_s[i*68 + d] = tf32r(g_o[g] * g_gv[g]);
    }
    for (int idx = tid; idx < 8192; idx += 256) {
        int dd = idx >> 7, n = idx & 127;
        b_s[dd*136 + n] = tf32r(Wo[(size_t)dd*CC + bn + n]);
    }
    __syncthreads();

    const int rb = (wid & 3) * 32;
    const int n0 = (wid >> 2) * 64;
    float acc[2][8][4];
    #pragma unroll
    for (int mi = 0; mi < 2; mi++)
        #pragma unroll
        for (int j = 0; j < 8; j++)
            #pragma unroll
            for (int e = 0; e < 4; e++) acc[mi][j][e] = 0.f;

    #pragma unroll
    for (int ks = 0; ks < 8; ks++) {
        unsigned a[2][4];
        #pragma unroll
        for (int mi = 0; mi < 2; mi++) {
            const float* Ab = a_s + (rb + mi*16)*68 + ks*8;
            a[mi][0] = FB(Ab[gi*68 + t]);
            a[mi][1] = FB(Ab[(gi+8)*68 + t]);
            a[mi][2] = FB(Ab[gi*68 + t + 4]);
            a[mi][3] = FB(Ab[(gi+8)*68 + t + 4]);
        }
        #pragma unroll
        for (int j = 0; j < 8; j++) {
            unsigned b0 = FB(b_s[(ks*8+t)*136 + n0 + j*8 + gi]);
            unsigned b1 = FB(b_s[(ks*8+t+4)*136 + n0 + j*8 + gi]);
            mma8(acc[0][j], a[0][0],a[0][1],a[0][2],a[0][3], b0,b1);
            mma8(acc[1][j], a[1][0],a[1][1],a[1][2],a[1][3], b0,b1);
        }
    }
    #pragma unroll
    for (int mi = 0; mi < 2; mi++)
        #pragma unroll
        for (int j = 0; j < 8; j++) {
            int m = bm + rb + mi*16 + gi;
            int n = bn + n0 + j*8 + t*2;
            out[(size_t)m*CC + n]       = acc[mi][j][0];
            out[(size_t)m*CC + n + 1]   = acc[mi][j][1];
            out[(size_t)(m+8)*CC + n]   = acc[mi][j][2];
            out[(size_t)(m+8)*CC + n+1] = acc[mi][j][3];
        }
}

// =====================================================================
extern "C" void kernel_launch(void* const* d_in, const int* in_sizes, int n_in,
                              void* d_out, int out_size)
{
    (void)in_sizes; (void)n_in; (void)out_size;
    const float* hs     = (const float*)d_in[0];
    const float* shift  = (const float*)d_in[1];
    const float* wkv0   = (const float*)d_in[2];
    const float* maa_x  = (const float*)d_in[3];
    const float* maa_w  = (const float*)d_in[4];
    const float* maa_k  = (const float*)d_in[5];
    const float* maa_v  = (const float*)d_in[6];
    const float* maa_r  = (const float*)d_in[7];
    const float* maa_g  = (const float*)d_in[8];
    const float* w1     = (const float*)d_in[9];
    const float* w2     = (const float*)d_in[10];
    const float* tdecay = (const float*)d_in[11];
    const float* dw1    = (const float*)d_in[12];
    const float* dw2    = (const float*)d_in[13];
    const float* faaaa  = (const float*)d_in[14];
    const float* Wr     = (const float*)d_in[15];
    const float* Wk     = (const float*)d_in[16];
    const float* Wv     = (const float*)d_in[17];
    const float* Wg     = (const float*)d_in[18];
    const float* Wo     = (const float*)d_in[19];
    float* out = (float*)d_out;

    const size_t OFF_LX = (size_t)BQ*TT*CC;
    const size_t OFF_SF = OFF_LX + (size_t)BQ*CC;

    cudaFuncSetAttribute(kp_proj,  cudaFuncAttributeMaxDynamicSharedMemorySize, KP_SMEM_BYTES);
    cudaFuncSetAttribute(k5_intra, cudaFuncAttributeMaxDynamicSharedMemorySize, K5_SMEM_BYTES);
    cudaFuncSetAttribute(k6_out,   cudaFuncAttributeMaxDynamicSharedMemorySize, K6_SMEM_BYTES);

    k1_mix  <<<MTOK/32, 256>>>(hs, shift, maa_x, w1);
    kp_proj <<<dim3(MTOK/128, 5), 256, KP_SMEM_BYTES>>>(hs, shift, maa_w, maa_k,
                                                        maa_v, maa_r, maa_g, w2,
                                                        dw1, Wk, Wv, Wr, Wg,
                                                        dw2, tdecay);
    k3_chunk<<<BQ*NCH, 256>>>();
    k4_scan <<<32, 256>>>(wkv0, out + OFF_SF, hs, out + OFF_LX);
    k5_intra<<<BQ*NCH, 256, K5_SMEM_BYTES>>>(faaaa);
    k6_out  <<<dim3(MTOK/128, CC/128), 256, K6_SMEM_BYTES>>>(Wo, out);
}